// round 7
// baseline (speedup 1.0000x reference)
#include <cuda_runtime.h>
#include <cuda_bf16.h>
#include <mma.h>
#include <cstdint>
#include <math.h>

using namespace nvcuda;

#define NR 8192
#define DD 512
#define BATCH 2048
#define NCLS 200

// ---------------- scratch (__device__ globals, no allocation) ----------------
__device__ __nv_bfloat16 g_f[(size_t)NR * DD];          // normalized features (8 MB)
__device__ __nv_bfloat16 g_prodb[(size_t)NR * NR];      // similarity matrix bf16 (128 MB)
__device__ double g_ce;
__device__ double g_np;
__device__ unsigned char g_tcls[BATCH];

// ---------------- reductions ----------------
template <int BS>
__device__ __forceinline__ float blockReduceSum(float v, float* sbuf) {
#pragma unroll
    for (int o = 16; o > 0; o >>= 1) v += __shfl_xor_sync(0xffffffffu, v, o);
    int w = threadIdx.x >> 5;
    if ((threadIdx.x & 31) == 0) sbuf[w] = v;
    __syncthreads();
    if (w == 0) {
        v = (threadIdx.x < BS / 32) ? sbuf[threadIdx.x] : 0.0f;
#pragma unroll
        for (int o = 16; o > 0; o >>= 1) v += __shfl_xor_sync(0xffffffffu, v, o);
        if (threadIdx.x == 0) sbuf[0] = v;
    }
    __syncthreads();
    float r = sbuf[0];
    __syncthreads();
    return r;
}
template <int BS>
__device__ __forceinline__ float blockReduceMax(float v, float* sbuf) {
#pragma unroll
    for (int o = 16; o > 0; o >>= 1) v = fmaxf(v, __shfl_xor_sync(0xffffffffu, v, o));
    int w = threadIdx.x >> 5;
    if ((threadIdx.x & 31) == 0) sbuf[w] = v;
    __syncthreads();
    if (w == 0) {
        v = (threadIdx.x < BS / 32) ? sbuf[threadIdx.x] : -3.0e38f;
#pragma unroll
        for (int o = 16; o > 0; o >>= 1) v = fmaxf(v, __shfl_xor_sync(0xffffffffu, v, o));
        if (threadIdx.x == 0) sbuf[0] = v;
    }
    __syncthreads();
    float r = sbuf[0];
    __syncthreads();
    return r;
}

// ---------------- targets decode (dtype-agnostic) ----------------
__global__ void decode_targets_kernel(const unsigned int* __restrict__ traw) {
    if (threadIdx.x == 0) { g_ce = 0.0; g_np = 0.0; }
    __syncthreads();
    int nz = 0;
    for (int i = threadIdx.x; i < BATCH / 2; i += blockDim.x)
        if (traw[2 * i + 1] != 0u) nz = 1;
    if (__syncthreads_or(nz)) {
        for (int i = threadIdx.x; i < BATCH; i += blockDim.x)
            g_tcls[i] = (unsigned char)traw[i];
    } else {
        for (int i = threadIdx.x; i < BATCH; i += blockDim.x)
            g_tcls[i] = (unsigned char)traw[2 * i];
    }
}

// ---------------- normalize ----------------
__global__ void normalize_kernel(const float* __restrict__ x) {
    __shared__ float sbuf[8];
    int row = blockIdx.x;
    const float* xr = x + (size_t)row * DD;
    float s = 0.0f;
    for (int c = threadIdx.x; c < DD; c += 128) { float v = xr[c]; s += v * v; }
    s = blockReduceSum<128>(s, sbuf);
    float inv = 1.0f / fmaxf(sqrtf(s), 1e-12f);
    for (int c = threadIdx.x; c < DD; c += 128)
        g_f[(size_t)row * DD + c] = __float2bfloat16(xr[c] * inv);
}

// ---------------- symmetric GEMM (wmma), bf16 output via smem staging ----------------
__device__ __forceinline__ void cp_async16(void* smem_dst, const void* gmem_src) {
    unsigned s = (unsigned)__cvta_generic_to_shared(smem_dst);
    asm volatile("cp.async.cg.shared.global [%0], [%1], 16;\n" :: "r"(s), "l"(gmem_src));
}

#define LDS 40          // pipeline tile row stride (bf16 elements)
#define LDG 132         // staging row stride (fp32 elements)

__global__ void __launch_bounds__(256) gemm_kernel() {
    extern __shared__ char dsm[];
    __nv_bfloat16* As = (__nv_bfloat16*)dsm;            // [2][128*LDS]
    __nv_bfloat16* Bs = As + 2 * 128 * LDS;             // [2][128*LDS]
    float* stg = (float*)dsm;                           // 128*LDG fp32 (reused after K loop)

    constexpr int NKIT = DD / 32;                       // 16 K-iterations

    // triangular tile decode: blockIdx.x in [0, 2080)
    int idx = blockIdx.x;
    int r = 0;
    while (idx >= 64 - r) { idx -= 64 - r; r++; }
    const int bm = r * 128;
    const int bn = (r + idx) * 128;

    const int tid = threadIdx.x;
    const int warp = tid >> 5;
    const int wm = (warp & 3) * 32;
    const int wn = (warp >> 2) * 64;

    const int c0 = tid;
    const int row0 = c0 >> 2, col0 = (c0 & 3) * 8;
    const int c1 = tid + 256;
    const int row1 = c1 >> 2, col1 = (c1 & 3) * 8;

    auto load_stage = [&](int k0, int s) {
        const __nv_bfloat16* a0 = g_f + (size_t)(bm + row0) * DD + k0 * 32 + col0;
        const __nv_bfloat16* a1 = g_f + (size_t)(bm + row1) * DD + k0 * 32 + col1;
        const __nv_bfloat16* b0 = g_f + (size_t)(bn + row0) * DD + k0 * 32 + col0;
        const __nv_bfloat16* b1 = g_f + (size_t)(bn + row1) * DD + k0 * 32 + col1;
        cp_async16(&As[s * 128 * LDS + row0 * LDS + col0], a0);
        cp_async16(&As[s * 128 * LDS + row1 * LDS + col1], a1);
        cp_async16(&Bs[s * 128 * LDS + row0 * LDS + col0], b0);
        cp_async16(&Bs[s * 128 * LDS + row1 * LDS + col1], b1);
    };

    wmma::fragment<wmma::accumulator, 16, 16, 16, float> acc[2][4];
#pragma unroll
    for (int i = 0; i < 2; i++)
#pragma unroll
        for (int j = 0; j < 4; j++) wmma::fill_fragment(acc[i][j], 0.0f);

    load_stage(0, 0);
    asm volatile("cp.async.commit_group;\n");

    for (int k0 = 0; k0 < NKIT; k0++) {
        if (k0 + 1 < NKIT) load_stage(k0 + 1, (k0 + 1) & 1);
        asm volatile("cp.async.commit_group;\n");
        asm volatile("cp.async.wait_group 1;\n");
        __syncthreads();

        const int s = k0 & 1;
#pragma unroll
        for (int kk = 0; kk < 2; kk++) {
            wmma::fragment<wmma::matrix_a, 16, 16, 16, __nv_bfloat16, wmma::row_major> a[2];
            wmma::fragment<wmma::matrix_b, 16, 16, 16, __nv_bfloat16, wmma::col_major> b[4];
#pragma unroll
            for (int i = 0; i < 2; i++)
                wmma::load_matrix_sync(a[i], &As[s * 128 * LDS + (wm + i * 16) * LDS + kk * 16], LDS);
#pragma unroll
            for (int j = 0; j < 4; j++)
                wmma::load_matrix_sync(b[j], &Bs[s * 128 * LDS + (wn + j * 16) * LDS + kk * 16], LDS);
#pragma unroll
            for (int i = 0; i < 2; i++)
#pragma unroll
                for (int j = 0; j < 4; j++) wmma::mma_sync(acc[i][j], a[i], b[j], acc[i][j]);
        }
        __syncthreads();
    }

    // stage fp32 tile in smem (pipeline buffers are dead now)
#pragma unroll
    for (int i = 0; i < 2; i++)
#pragma unroll
        for (int j = 0; j < 4; j++)
            wmma::store_matrix_sync(stg + (size_t)(wm + i * 16) * LDG + wn + j * 16,
                                    acc[i][j], LDG, wmma::mem_row_major);
    __syncthreads();

    // direct write: rows bm+rr, cols bn.. (coalesced bf16, 16B per thread-chunk)
    {
        const int rr = tid >> 1;                 // 0..127
        const int cc = (tid & 1) * 64;           // 0 or 64
        const float* src = stg + (size_t)rr * LDG + cc;
        uint32_t* dst = (uint32_t*)(g_prodb + (size_t)(bm + rr) * NR + bn + cc);
#pragma unroll
        for (int c8 = 0; c8 < 8; c8++) {
            uint32_t pk[4];
#pragma unroll
            for (int q = 0; q < 4; q++) {
                __nv_bfloat162 h = __floats2bfloat162_rn(src[c8 * 8 + 2 * q],
                                                         src[c8 * 8 + 2 * q + 1]);
                pk[q] = *(uint32_t*)&h;
            }
            ((uint4*)dst)[c8] = *(uint4*)pk;
        }
    }
    // mirror write (transpose) for off-diagonal tiles — also coalesced bf16 rows
    if (bm != bn) {
        const int rp = tid >> 1;                 // output row index within tile (orig col)
        const int cc = (tid & 1) * 64;           // orig-row chunk
        uint32_t* dst = (uint32_t*)(g_prodb + (size_t)(bn + rp) * NR + bm + cc);
#pragma unroll
        for (int c8 = 0; c8 < 8; c8++) {
            uint32_t pk[4];
#pragma unroll
            for (int q = 0; q < 4; q++) {
                float v0 = stg[(size_t)(cc + c8 * 8 + 2 * q) * LDG + rp];
                float v1 = stg[(size_t)(cc + c8 * 8 + 2 * q + 1) * LDG + rp];
                __nv_bfloat162 h = __floats2bfloat162_rn(v0, v1);
                pk[q] = *(uint32_t*)&h;
            }
            ((uint4*)dst)[c8] = *(uint4*)pk;
        }
    }
}

// ---------------- epilogue: one block per anchor row (dynamic smem) ----------------
// dynamic smem layout: float rowe[NR] (32KB) | __nv_bfloat16 rowv[NR] (16KB)
#define EPI_SMEM (NR * 4 + NR * 2)

__global__ void __launch_bounds__(256) epilogue_kernel() {
    extern __shared__ char edsm[];
    float* rowe = (float*)edsm;                          // exp(v), 32 KB
    __nv_bfloat16* rowv = (__nv_bfloat16*)(edsm + NR * 4); // values, 16 KB
    __shared__ unsigned char scls[BATCH];                // 2 KB (static)
    __shared__ float sbuf[8];
    for (int c = threadIdx.x; c < BATCH; c += 256) scls[c] = g_tcls[c];
    __syncthreads();

    const int i = blockIdx.x;
    const int ti = scls[i >> 2];
    const int pi = i & 3;
    const uint4* pr4 = (const uint4*)(g_prodb + (size_t)i * NR);

    float a1 = 0.0f, a2 = 0.0f;
    for (int idx = threadIdx.x; idx < NR / 8; idx += 256) {
        uint4 v4 = pr4[idx];
        ((uint4*)rowv)[idx] = v4;
        const int j0 = idx * 8;
        float f[8];
        {
            float2 t;
            t = __bfloat1622float2(*(__nv_bfloat162*)&v4.x); f[0] = t.x; f[1] = t.y;
            t = __bfloat1622float2(*(__nv_bfloat162*)&v4.y); f[2] = t.x; f[3] = t.y;
            t = __bfloat1622float2(*(__nv_bfloat162*)&v4.z); f[4] = t.x; f[5] = t.y;
            t = __bfloat1622float2(*(__nv_bfloat162*)&v4.w); f[6] = t.x; f[7] = t.y;
        }
        float e[8];
#pragma unroll
        for (int q = 0; q < 8; q++) { e[q] = __expf(f[q]); rowe[j0 + q] = e[q]; }
        const bool sc0 = (scls[idx * 2] == ti);
        const bool sc1 = (scls[idx * 2 + 1] == ti);
        const float s0 = (e[0] + e[1]) + (e[2] + e[3]);
        const float s1 = (e[4] + e[5]) + (e[6] + e[7]);
        const float ep0 = e[pi], ep1 = e[4 + pi];
        a1 += (s0 + s1) - (sc0 ? ep0 : 0.0f) - (sc1 ? ep1 : 0.0f);
        a2 += (sc0 ? 0.0f : (s0 - ep0)) + (sc1 ? 0.0f : (s1 - ep1));
    }
    const float E1 = blockReduceSum<256>(a1, sbuf);
    const float E2 = blockReduceSum<256>(a2, sbuf);
    const float lE1 = __logf(E1), rE1 = 1.0f / E1;
    const float lE2 = __logf(E2), rE2 = 1.0f / E2;

    // log1p(e^{-v}E) = (logE - v) + e^{v}/E   (x >= ~700; err < 1e-6)
    float local = 0.0f;
    for (int idx = threadIdx.x; idx < NR / 8; idx += 256) {
        const int j0 = idx * 8;
        const bool sc0 = (scls[idx * 2] == ti);
        const bool sc1 = (scls[idx * 2 + 1] == ti);
        {
            float v = __bfloat162float(rowv[j0 + pi]);
            float ev = rowe[j0 + pi];
            local += sc0 ? (lE1 - v + ev * rE1) : (lE2 - v + ev * rE2);
        }
        {
            float v = __bfloat162float(rowv[j0 + 4 + pi]);
            float ev = rowe[j0 + 4 + pi];
            local += sc1 ? (lE1 - v + ev * rE1) : (lE2 - v + ev * rE2);
        }
        if (sc0) {
#pragma unroll
            for (int q = 0; q < 4; q++) if (q != pi) {
                float v = __bfloat162float(rowv[j0 + q]);
                local += lE2 - v + rowe[j0 + q] * rE2;
            }
        }
        if (sc1) {
#pragma unroll
            for (int q = 0; q < 4; q++) if (q != pi) {
                float v = __bfloat162float(rowv[j0 + 4 + q]);
                local += lE2 - v + rowe[j0 + 4 + q] * rE2;
            }
        }
    }
    float tot = blockReduceSum<256>(local, sbuf);
    if (threadIdx.x == 0) atomicAdd(&g_np, (double)tot);
}

// ---------------- CE with label smoothing ----------------
__global__ void ce_kernel(const float* __restrict__ pred) {
    __shared__ float sbuf[2];
    const int i = blockIdx.x;
    const float* p = pred + (size_t)i * NCLS;
    float m = -3.0e38f, slin = 0.0f;
    for (int c = threadIdx.x; c < NCLS; c += 64) {
        float v = p[c];
        m = fmaxf(m, v);
        slin += v;
    }
    m = blockReduceMax<64>(m, sbuf);
    slin = blockReduceSum<64>(slin, sbuf);
    float se = 0.0f;
    for (int c = threadIdx.x; c < NCLS; c += 64) se += __expf(p[c] - m);
    se = blockReduceSum<64>(se, sbuf);
    if (threadIdx.x == 0) {
        float lse = m + __logf(se);
        int t = (int)g_tcls[i];
        float loss = 0.9f * (lse - p[t]) + 0.1f * (lse - slin / (float)NCLS);
        atomicAdd(&g_ce, (double)loss);
    }
}

__global__ void finalize_kernel(float* out) {
    out[0] = (float)(g_ce / (double)BATCH + 0.5 * (g_np / (double)NR));
}

// ---------------- launch ----------------
extern "C" void kernel_launch(void* const* d_in, const int* in_sizes, int n_in,
                              void* d_out, int out_size) {
    const float* pred = nullptr;
    const float* x_part = nullptr;
    const unsigned int* traw = nullptr;
    for (int i = 0; i < n_in; i++) {
        if (in_sizes[i] == BATCH * NCLS)      pred   = (const float*)d_in[i];
        else if (in_sizes[i] == NR * DD)      x_part = (const float*)d_in[i];
        else if (in_sizes[i] == BATCH)        traw   = (const unsigned int*)d_in[i];
    }
    float* out = (float*)d_out;

    // gemm smem: max(pipeline 2*2*128*LDS*2B = 40960B, staging 128*LDG*4B = 67584B)
    const int gemm_smem = 128 * LDG * 4;
    cudaFuncSetAttribute(gemm_kernel, cudaFuncAttributeMaxDynamicSharedMemorySize, gemm_smem);
    cudaFuncSetAttribute(epilogue_kernel, cudaFuncAttributeMaxDynamicSharedMemorySize, EPI_SMEM);

    decode_targets_kernel<<<1, 1024>>>(traw);
    normalize_kernel<<<NR, 128>>>(x_part);
    gemm_kernel<<<2080, 256, gemm_smem>>>();
    ce_kernel<<<BATCH, 64>>>(pred);
    epilogue_kernel<<<NR, 256, EPI_SMEM>>>();
    finalize_kernel<<<1, 1>>>(out);
}

// round 8
// speedup vs baseline: 1.4777x; 1.4777x over previous
#include <cuda_runtime.h>
#include <cuda_bf16.h>
#include <mma.h>
#include <cstdint>
#include <math.h>

using namespace nvcuda;

#define NR 8192
#define DD 512
#define BATCH 2048
#define NCLS 200

// ---------------- scratch (__device__ globals, no allocation) ----------------
__device__ __nv_bfloat16 g_f[(size_t)NR * DD];   // normalized features (8 MB)
__device__ float g_rows[(size_t)NR * 8];         // per-row {T,P,Q,R,Pv,Qv,Rv,pad} (256 KB)
__device__ int g_chist[NCLS];
__device__ double g_ce;
__device__ double g_np;
__device__ unsigned char g_tcls[BATCH];

// ---------------- reductions ----------------
template <int BS>
__device__ __forceinline__ float blockReduceSum(float v, float* sbuf) {
#pragma unroll
    for (int o = 16; o > 0; o >>= 1) v += __shfl_xor_sync(0xffffffffu, v, o);
    int w = threadIdx.x >> 5;
    if ((threadIdx.x & 31) == 0) sbuf[w] = v;
    __syncthreads();
    if (w == 0) {
        v = (threadIdx.x < BS / 32) ? sbuf[threadIdx.x] : 0.0f;
#pragma unroll
        for (int o = 16; o > 0; o >>= 1) v += __shfl_xor_sync(0xffffffffu, v, o);
        if (threadIdx.x == 0) sbuf[0] = v;
    }
    __syncthreads();
    float r = sbuf[0];
    __syncthreads();
    return r;
}
template <int BS>
__device__ __forceinline__ float blockReduceMax(float v, float* sbuf) {
#pragma unroll
    for (int o = 16; o > 0; o >>= 1) v = fmaxf(v, __shfl_xor_sync(0xffffffffu, v, o));
    int w = threadIdx.x >> 5;
    if ((threadIdx.x & 31) == 0) sbuf[w] = v;
    __syncthreads();
    if (w == 0) {
        v = (threadIdx.x < BS / 32) ? sbuf[threadIdx.x] : -3.0e38f;
#pragma unroll
        for (int o = 16; o > 0; o >>= 1) v = fmaxf(v, __shfl_xor_sync(0xffffffffu, v, o));
        if (threadIdx.x == 0) sbuf[0] = v;
    }
    __syncthreads();
    float r = sbuf[0];
    __syncthreads();
    return r;
}

// ---------------- decode targets + class histogram + zero accumulators ----------------
__global__ void decode_targets_kernel(const unsigned int* __restrict__ traw) {
    __shared__ int hist[NCLS];
    if (threadIdx.x == 0) { g_ce = 0.0; g_np = 0.0; }
    for (int c = threadIdx.x; c < NCLS; c += blockDim.x) hist[c] = 0;
    __syncthreads();
    int nz = 0;
    for (int i = threadIdx.x; i < BATCH / 2; i += blockDim.x)
        if (traw[2 * i + 1] != 0u) nz = 1;
    if (__syncthreads_or(nz)) {           // int32 layout
        for (int i = threadIdx.x; i < BATCH; i += blockDim.x) {
            unsigned char c = (unsigned char)traw[i];
            g_tcls[i] = c;
            atomicAdd(&hist[c], 1);
        }
    } else {                              // little-endian int64 layout
        for (int i = threadIdx.x; i < BATCH; i += blockDim.x) {
            unsigned char c = (unsigned char)traw[2 * i];
            g_tcls[i] = c;
            atomicAdd(&hist[c], 1);
        }
    }
    __syncthreads();
    for (int c = threadIdx.x; c < NCLS; c += blockDim.x) g_chist[c] = hist[c];
    for (size_t i = threadIdx.x; i < (size_t)NR * 8; i += blockDim.x) g_rows[i] = 0.0f;
}

// ---------------- normalize ----------------
__global__ void normalize_kernel(const float* __restrict__ x) {
    __shared__ float sbuf[8];
    int row = blockIdx.x;
    const float* xr = x + (size_t)row * DD;
    float s = 0.0f;
    for (int c = threadIdx.x; c < DD; c += 128) { float v = xr[c]; s += v * v; }
    s = blockReduceSum<128>(s, sbuf);
    float inv = 1.0f / fmaxf(sqrtf(s), 1e-12f);
    for (int c = threadIdx.x; c < DD; c += 128)
        g_f[(size_t)row * DD + c] = __float2bfloat16(xr[c] * inv);
}

// ---------------- fused symmetric GEMM + masked reductions ----------------
__device__ __forceinline__ void cp_async16(void* smem_dst, const void* gmem_src) {
    unsigned s = (unsigned)__cvta_generic_to_shared(smem_dst);
    asm volatile("cp.async.cg.shared.global [%0], [%1], 16;\n" :: "r"(s), "l"(gmem_src));
}

#define LDSB 72         // pipeline row stride (bf16 elems), BK=64 + pad
#define LDG 132         // staging row stride (fp32 elems)

__global__ void __launch_bounds__(256) gemm_fused_kernel() {
    extern __shared__ char dsm[];
    __nv_bfloat16* As = (__nv_bfloat16*)dsm;          // [2][128*LDSB]
    __nv_bfloat16* Bs = As + 2 * 128 * LDSB;          // [2][128*LDSB]
    float* stg = (float*)dsm;                         // 128*LDG fp32 (reused)
    __shared__ unsigned char clsA[128], clsB[128];

    constexpr int NKIT = DD / 64;                     // 8 K-iterations

    // triangular tile decode: blockIdx.x in [0, 2080)
    int idx = blockIdx.x;
    int r = 0;
    while (idx >= 64 - r) { idx -= 64 - r; r++; }
    const int bm = r * 128;
    const int bn = (r + idx) * 128;

    const int tid = threadIdx.x;
    const int warp = tid >> 5;
    const int wm = (warp & 3) * 32;
    const int wn = (warp >> 2) * 64;

    auto load_stage = [&](int k0, int s) {
#pragma unroll
        for (int it = 0; it < 4; it++) {
            int c = it * 256 + tid;                   // 1024 chunks of 16B per tensor
            int row = c >> 3;
            int col = (c & 7) * 8;
            cp_async16(&As[s * 128 * LDSB + row * LDSB + col],
                       g_f + (size_t)(bm + row) * DD + k0 * 64 + col);
            cp_async16(&Bs[s * 128 * LDSB + row * LDSB + col],
                       g_f + (size_t)(bn + row) * DD + k0 * 64 + col);
        }
    };

    wmma::fragment<wmma::accumulator, 16, 16, 16, float> acc[2][4];
#pragma unroll
    for (int i = 0; i < 2; i++)
#pragma unroll
        for (int j = 0; j < 4; j++) wmma::fill_fragment(acc[i][j], 0.0f);

    load_stage(0, 0);
    asm volatile("cp.async.commit_group;\n");

    for (int k0 = 0; k0 < NKIT; k0++) {
        if (k0 + 1 < NKIT) load_stage(k0 + 1, (k0 + 1) & 1);
        asm volatile("cp.async.commit_group;\n");
        asm volatile("cp.async.wait_group 1;\n");
        __syncthreads();

        const int s = k0 & 1;
#pragma unroll
        for (int kk = 0; kk < 4; kk++) {
            wmma::fragment<wmma::matrix_a, 16, 16, 16, __nv_bfloat16, wmma::row_major> a[2];
            wmma::fragment<wmma::matrix_b, 16, 16, 16, __nv_bfloat16, wmma::col_major> b[4];
#pragma unroll
            for (int i = 0; i < 2; i++)
                wmma::load_matrix_sync(a[i], &As[s * 128 * LDSB + (wm + i * 16) * LDSB + kk * 16], LDSB);
#pragma unroll
            for (int j = 0; j < 4; j++)
                wmma::load_matrix_sync(b[j], &Bs[s * 128 * LDSB + (wn + j * 16) * LDSB + kk * 16], LDSB);
#pragma unroll
            for (int i = 0; i < 2; i++)
#pragma unroll
                for (int j = 0; j < 4; j++) wmma::mma_sync(acc[i][j], a[i], b[j], acc[i][j]);
        }
        __syncthreads();
    }

    // stage fp32 tile in smem (pipeline buffers dead)
#pragma unroll
    for (int i = 0; i < 2; i++)
#pragma unroll
        for (int j = 0; j < 4; j++)
            wmma::store_matrix_sync(stg + (size_t)(wm + i * 16) * LDG + wn + j * 16,
                                    acc[i][j], LDG, wmma::mem_row_major);
    if (tid < 128) clsA[tid] = g_tcls[(bm + tid) >> 2];
    else           clsB[tid - 128] = g_tcls[(bn + (tid - 128)) >> 2];
    __syncthreads();

    // fused masked reductions:
    //  t<128:   anchor row bm+t, values stg[t][j] (j rotated by t -> conflict-free)
    //  t>=128:  anchor row bn+(t-128), values stg[j][t-128] (off-diagonal only)
    float T = 0.f, P = 0.f, Q = 0.f, R = 0.f, Pv = 0.f, Qv = 0.f, Rv = 0.f;
    int anchor = -1;
    if (tid < 128) {
        const int t = tid;
        anchor = bm + t;
        const int myc = clsA[t], myp = t & 3;
        const float* row = stg + (size_t)t * LDG;
        for (int j0 = 0; j0 < 128; j0++) {
            const int j = (j0 + t) & 127;
            float v = row[j];
            float e = __expf(v);
            bool sc = (clsB[j] == myc);
            bool sa = ((j & 3) == myp);
            T += e;
            if (sc && sa)      { P += e; Pv += v; }
            else if (sa)       { Q += e; Qv += v; }
            else if (sc)       { R += e; Rv += v; }
        }
    } else if (bm != bn) {
        const int t = tid - 128;
        anchor = bn + t;
        const int myc = clsB[t], myp = t & 3;
        for (int j = 0; j < 128; j++) {
            float v = stg[(size_t)j * LDG + t];
            float e = __expf(v);
            bool sc = (clsA[j] == myc);
            bool sa = ((j & 3) == myp);
            T += e;
            if (sc && sa)      { P += e; Pv += v; }
            else if (sa)       { Q += e; Qv += v; }
            else if (sc)       { R += e; Rv += v; }
        }
    }
    if (anchor >= 0) {
        float* d = g_rows + (size_t)anchor * 8;
        atomicAdd(d + 0, T);
        atomicAdd(d + 1, P);
        atomicAdd(d + 2, Q);
        atomicAdd(d + 3, R);
        atomicAdd(d + 4, Pv);
        atomicAdd(d + 5, Qv);
        atomicAdd(d + 6, Rv);
    }
}

// ---------------- assemble per-row losses ----------------
// E1 = T-P; E2 = T-P-Q-R.  x = e^{-v}E >= ~700, so
// sum_pos log1p(e^{-v}E) = n*logE - sum(v) + sum(e^v)/E   (err < 1e-6/term)
__global__ void assemble_kernel() {
    const int i = blockIdx.x * blockDim.x + threadIdx.x;   // 8192 threads
    const float* b = g_rows + (size_t)i * 8;
    float T = b[0], P = b[1], Q = b[2], R = b[3], Pv = b[4], Qv = b[5], Rv = b[6];
    float E1 = T - P;
    float E2 = E1 - Q - R;
    float ct = (float)g_chist[g_tcls[i >> 2]];
    float c = ct * logf(E1) - Pv + P / E1
            + (2048.0f + 2.0f * ct) * logf(E2) - (Qv + Rv) + (Q + R) / E2;
    double d = (double)c;
#pragma unroll
    for (int o = 16; o > 0; o >>= 1) d += __shfl_xor_sync(0xffffffffu, d, o);
    if ((threadIdx.x & 31) == 0) atomicAdd(&g_np, d);
}

// ---------------- CE with label smoothing ----------------
__global__ void ce_kernel(const float* __restrict__ pred) {
    __shared__ float sbuf[2];
    const int i = blockIdx.x;
    const float* p = pred + (size_t)i * NCLS;
    float m = -3.0e38f, slin = 0.0f;
    for (int c = threadIdx.x; c < NCLS; c += 64) {
        float v = p[c];
        m = fmaxf(m, v);
        slin += v;
    }
    m = blockReduceMax<64>(m, sbuf);
    slin = blockReduceSum<64>(slin, sbuf);
    float se = 0.0f;
    for (int c = threadIdx.x; c < NCLS; c += 64) se += __expf(p[c] - m);
    se = blockReduceSum<64>(se, sbuf);
    if (threadIdx.x == 0) {
        float lse = m + __logf(se);
        int t = (int)g_tcls[i];
        float loss = 0.9f * (lse - p[t]) + 0.1f * (lse - slin / (float)NCLS);
        atomicAdd(&g_ce, (double)loss);
    }
}

__global__ void finalize_kernel(float* out) {
    out[0] = (float)(g_ce / (double)BATCH + 0.5 * (g_np / (double)NR));
}

// ---------------- launch ----------------
extern "C" void kernel_launch(void* const* d_in, const int* in_sizes, int n_in,
                              void* d_out, int out_size) {
    const float* pred = nullptr;
    const float* x_part = nullptr;
    const unsigned int* traw = nullptr;
    for (int i = 0; i < n_in; i++) {
        if (in_sizes[i] == BATCH * NCLS)      pred   = (const float*)d_in[i];
        else if (in_sizes[i] == NR * DD)      x_part = (const float*)d_in[i];
        else if (in_sizes[i] == BATCH)        traw   = (const unsigned int*)d_in[i];
    }
    float* out = (float*)d_out;

    // dynamic smem: max(pipeline 2*2*128*72*2B = 73728B, staging 128*132*4B = 67584B)
    const int gemm_smem = 2 * 2 * 128 * LDSB * 2;
    cudaFuncSetAttribute(gemm_fused_kernel, cudaFuncAttributeMaxDynamicSharedMemorySize, gemm_smem);

    decode_targets_kernel<<<1, 1024>>>(traw);
    normalize_kernel<<<NR, 128>>>(x_part);
    gemm_fused_kernel<<<2080, 256, gemm_smem>>>();
    ce_kernel<<<BATCH, 64>>>(pred);
    assemble_kernel<<<NR / 256, 256>>>();
    finalize_kernel<<<1, 1>>>(out);
}

// round 9
// speedup vs baseline: 1.6283x; 1.1019x over previous
#include <cuda_runtime.h>
#include <cuda_bf16.h>
#include <mma.h>
#include <cstdint>
#include <math.h>

using namespace nvcuda;

#define NR 8192
#define DD 512
#define BATCH 2048
#define NCLS 200

// ---------------- scratch (__device__ globals, no allocation) ----------------
__device__ __nv_bfloat16 g_f[(size_t)NR * DD];   // normalized features (8 MB)
__device__ float g_rows[(size_t)NR * 8];         // per-row {T,P,Q,R,Pv,Qv,Rv,pad} (256 KB)
__device__ int g_chist[NCLS];
__device__ double g_ce;
__device__ unsigned char g_tcls[BATCH];

// ---------------- reductions ----------------
template <int BS>
__device__ __forceinline__ float blockReduceSum(float v, float* sbuf) {
#pragma unroll
    for (int o = 16; o > 0; o >>= 1) v += __shfl_xor_sync(0xffffffffu, v, o);
    int w = threadIdx.x >> 5;
    if ((threadIdx.x & 31) == 0) sbuf[w] = v;
    __syncthreads();
    if (w == 0) {
        v = (threadIdx.x < BS / 32) ? sbuf[threadIdx.x] : 0.0f;
#pragma unroll
        for (int o = 16; o > 0; o >>= 1) v += __shfl_xor_sync(0xffffffffu, v, o);
        if (threadIdx.x == 0) sbuf[0] = v;
    }
    __syncthreads();
    float r = sbuf[0];
    __syncthreads();
    return r;
}
template <int BS>
__device__ __forceinline__ float blockReduceMax(float v, float* sbuf) {
#pragma unroll
    for (int o = 16; o > 0; o >>= 1) v = fmaxf(v, __shfl_xor_sync(0xffffffffu, v, o));
    int w = threadIdx.x >> 5;
    if ((threadIdx.x & 31) == 0) sbuf[w] = v;
    __syncthreads();
    if (w == 0) {
        v = (threadIdx.x < BS / 32) ? sbuf[threadIdx.x] : -3.0e38f;
#pragma unroll
        for (int o = 16; o > 0; o >>= 1) v = fmaxf(v, __shfl_xor_sync(0xffffffffu, v, o));
        if (threadIdx.x == 0) sbuf[0] = v;
    }
    __syncthreads();
    float r = sbuf[0];
    __syncthreads();
    return r;
}

// ---------------- decode targets + class histogram + zero accumulators ----------------
__global__ void decode_targets_kernel(const unsigned int* __restrict__ traw) {
    __shared__ int hist[NCLS];
    if (threadIdx.x == 0) g_ce = 0.0;
    for (int c = threadIdx.x; c < NCLS; c += blockDim.x) hist[c] = 0;
    __syncthreads();
    int nz = 0;
    for (int i = threadIdx.x; i < BATCH / 2; i += blockDim.x)
        if (traw[2 * i + 1] != 0u) nz = 1;
    if (__syncthreads_or(nz)) {           // int32 layout
        for (int i = threadIdx.x; i < BATCH; i += blockDim.x) {
            unsigned char c = (unsigned char)traw[i];
            g_tcls[i] = c;
            atomicAdd(&hist[c], 1);
        }
    } else {                              // little-endian int64 layout
        for (int i = threadIdx.x; i < BATCH; i += blockDim.x) {
            unsigned char c = (unsigned char)traw[2 * i];
            g_tcls[i] = c;
            atomicAdd(&hist[c], 1);
        }
    }
    __syncthreads();
    for (int c = threadIdx.x; c < NCLS; c += blockDim.x) g_chist[c] = hist[c];
    for (size_t i = threadIdx.x; i < (size_t)NR * 8; i += blockDim.x) g_rows[i] = 0.0f;
}

// ---------------- fused normalize + CE ----------------
__global__ void norm_ce_kernel(const float* __restrict__ x, const float* __restrict__ pred) {
    __shared__ float sbuf[8];
    const int b = blockIdx.x;
    if (b < NR) {
        const float* xr = x + (size_t)b * DD;
        float s = 0.0f;
        for (int c = threadIdx.x; c < DD; c += 128) { float v = xr[c]; s += v * v; }
        s = blockReduceSum<128>(s, sbuf);
        float inv = 1.0f / fmaxf(sqrtf(s), 1e-12f);
        for (int c = threadIdx.x; c < DD; c += 128)
            g_f[(size_t)b * DD + c] = __float2bfloat16(xr[c] * inv);
    } else {
        const int i = b - NR;
        const float* p = pred + (size_t)i * NCLS;
        float m = -3.0e38f, slin = 0.0f;
        for (int c = threadIdx.x; c < NCLS; c += 128) {
            float v = p[c];
            m = fmaxf(m, v);
            slin += v;
        }
        m = blockReduceMax<128>(m, sbuf);
        slin = blockReduceSum<128>(slin, sbuf);
        float se = 0.0f;
        for (int c = threadIdx.x; c < NCLS; c += 128) se += __expf(p[c] - m);
        se = blockReduceSum<128>(se, sbuf);
        if (threadIdx.x == 0) {
            float lse = m + __logf(se);
            int t = (int)g_tcls[i];
            float loss = 0.9f * (lse - p[t]) + 0.1f * (lse - slin / (float)NCLS);
            atomicAdd(&g_ce, (double)loss);
        }
    }
}

// ---------------- fused symmetric GEMM + masked reductions ----------------
__device__ __forceinline__ void cp_async16(void* smem_dst, const void* gmem_src) {
    unsigned s = (unsigned)__cvta_generic_to_shared(smem_dst);
    asm volatile("cp.async.cg.shared.global [%0], [%1], 16;\n" :: "r"(s), "l"(gmem_src));
}

#define LDSB 72         // pipeline row stride (bf16 elems), BK=64 + pad
#define LDG 132         // staging row stride (fp32 elems)

__global__ void __launch_bounds__(256) gemm_fused_kernel() {
    extern __shared__ char dsm[];
    __nv_bfloat16* As = (__nv_bfloat16*)dsm;          // [2][128*LDSB]
    __nv_bfloat16* Bs = As + 2 * 128 * LDSB;          // [2][128*LDSB]
    float* stg = (float*)dsm;                         // 128*LDG fp32 (reused)
    __shared__ unsigned char gA[32], gB[32];          // per-group (4 rows) class codes

    constexpr int NKIT = DD / 64;                     // 8 K-iterations

    // triangular tile decode: blockIdx.x in [0, 2080)
    int idx = blockIdx.x;
    int r = 0;
    while (idx >= 64 - r) { idx -= 64 - r; r++; }
    const int bm = r * 128;
    const int bn = (r + idx) * 128;

    const int tid = threadIdx.x;
    const int warp = tid >> 5;
    const int wm = (warp & 3) * 32;
    const int wn = (warp >> 2) * 64;

    auto load_stage = [&](int k0, int s) {
#pragma unroll
        for (int it = 0; it < 4; it++) {
            int c = it * 256 + tid;                   // 1024 chunks of 16B per tensor
            int row = c >> 3;
            int col = (c & 7) * 8;
            cp_async16(&As[s * 128 * LDSB + row * LDSB + col],
                       g_f + (size_t)(bm + row) * DD + k0 * 64 + col);
            cp_async16(&Bs[s * 128 * LDSB + row * LDSB + col],
                       g_f + (size_t)(bn + row) * DD + k0 * 64 + col);
        }
    };

    wmma::fragment<wmma::accumulator, 16, 16, 16, float> acc[2][4];
#pragma unroll
    for (int i = 0; i < 2; i++)
#pragma unroll
        for (int j = 0; j < 4; j++) wmma::fill_fragment(acc[i][j], 0.0f);

    load_stage(0, 0);
    asm volatile("cp.async.commit_group;\n");

    for (int k0 = 0; k0 < NKIT; k0++) {
        if (k0 + 1 < NKIT) load_stage(k0 + 1, (k0 + 1) & 1);
        asm volatile("cp.async.commit_group;\n");
        asm volatile("cp.async.wait_group 1;\n");
        __syncthreads();

        const int s = k0 & 1;
#pragma unroll
        for (int kk = 0; kk < 4; kk++) {
            wmma::fragment<wmma::matrix_a, 16, 16, 16, __nv_bfloat16, wmma::row_major> a[2];
            wmma::fragment<wmma::matrix_b, 16, 16, 16, __nv_bfloat16, wmma::col_major> b[4];
#pragma unroll
            for (int i = 0; i < 2; i++)
                wmma::load_matrix_sync(a[i], &As[s * 128 * LDSB + (wm + i * 16) * LDSB + kk * 16], LDSB);
#pragma unroll
            for (int j = 0; j < 4; j++)
                wmma::load_matrix_sync(b[j], &Bs[s * 128 * LDSB + (wn + j * 16) * LDSB + kk * 16], LDSB);
#pragma unroll
            for (int i = 0; i < 2; i++)
#pragma unroll
                for (int j = 0; j < 4; j++) wmma::mma_sync(acc[i][j], a[i], b[j], acc[i][j]);
        }
        __syncthreads();
    }

    // stage fp32 tile in smem (pipeline buffers dead)
#pragma unroll
    for (int i = 0; i < 2; i++)
#pragma unroll
        for (int j = 0; j < 4; j++)
            wmma::store_matrix_sync(stg + (size_t)(wm + i * 16) * LDG + wn + j * 16,
                                    acc[i][j], LDG, wmma::mem_row_major);
    if (tid < 32) gA[tid] = g_tcls[(bm >> 2) + tid];
    else if (tid < 64) gB[tid - 32] = g_tcls[(bn >> 2) + (tid - 32)];
    __syncthreads();

    // ---- row pass: 2 threads per anchor row (bm+a); groups of 4 cols share class ----
    {
        const int a = tid >> 1, h = tid & 1;
        const int myc = gA[a >> 2], pi = a & 3;
        float T = 0.f, P = 0.f, Q = 0.f, R = 0.f, Pv = 0.f, Qv = 0.f, Rv = 0.f;
        const float4* rp = (const float4*)(stg + (size_t)a * LDG + h * 64);
#pragma unroll
        for (int g = 0; g < 16; g++) {
            float4 v4 = rp[g];
            float e0 = __expf(v4.x), e1 = __expf(v4.y), e2 = __expf(v4.z), e3 = __expf(v4.w);
            float s = (e0 + e1) + (e2 + e3);
            float vs = (v4.x + v4.y) + (v4.z + v4.w);
            float ep = pi == 0 ? e0 : pi == 1 ? e1 : pi == 2 ? e2 : e3;
            float vp = pi == 0 ? v4.x : pi == 1 ? v4.y : pi == 2 ? v4.z : v4.w;
            float m = (gB[h * 16 + g] == myc) ? 1.0f : 0.0f;
            T += s;
            P += m * ep;          Pv += m * vp;
            R += m * (s - ep);    Rv += m * (vs - vp);
            Q += (1.0f - m) * ep; Qv += (1.0f - m) * vp;
        }
        T += __shfl_xor_sync(0xffffffffu, T, 1);
        P += __shfl_xor_sync(0xffffffffu, P, 1);
        Q += __shfl_xor_sync(0xffffffffu, Q, 1);
        R += __shfl_xor_sync(0xffffffffu, R, 1);
        Pv += __shfl_xor_sync(0xffffffffu, Pv, 1);
        Qv += __shfl_xor_sync(0xffffffffu, Qv, 1);
        Rv += __shfl_xor_sync(0xffffffffu, Rv, 1);
        if (h == 0) {
            float* d = g_rows + (size_t)(bm + a) * 8;
            atomicAdd(d + 0, T);  atomicAdd(d + 1, P);  atomicAdd(d + 2, Q);
            atomicAdd(d + 3, R);  atomicAdd(d + 4, Pv); atomicAdd(d + 5, Qv);
            atomicAdd(d + 6, Rv);
        }
    }

    // ---- col pass (off-diagonal only): anchors bn+c over rows of bm block ----
    if (bm != bn) {
        const int c = tid >> 1, h = tid & 1;
        const int myc = gB[c >> 2], pi = c & 3;
        float T = 0.f, P = 0.f, Q = 0.f, R = 0.f, Pv = 0.f, Qv = 0.f, Rv = 0.f;
#pragma unroll
        for (int g = 0; g < 16; g++) {
            const int j0 = h * 64 + g * 4;
            float v0 = stg[(j0 + 0) * LDG + c];
            float v1 = stg[(j0 + 1) * LDG + c];
            float v2 = stg[(j0 + 2) * LDG + c];
            float v3 = stg[(j0 + 3) * LDG + c];
            float e0 = __expf(v0), e1 = __expf(v1), e2 = __expf(v2), e3 = __expf(v3);
            float s = (e0 + e1) + (e2 + e3);
            float vs = (v0 + v1) + (v2 + v3);
            float ep = pi == 0 ? e0 : pi == 1 ? e1 : pi == 2 ? e2 : e3;
            float vp = pi == 0 ? v0 : pi == 1 ? v1 : pi == 2 ? v2 : v3;
            float m = (gA[h * 16 + g] == myc) ? 1.0f : 0.0f;
            T += s;
            P += m * ep;          Pv += m * vp;
            R += m * (s - ep);    Rv += m * (vs - vp);
            Q += (1.0f - m) * ep; Qv += (1.0f - m) * vp;
        }
        T += __shfl_xor_sync(0xffffffffu, T, 1);
        P += __shfl_xor_sync(0xffffffffu, P, 1);
        Q += __shfl_xor_sync(0xffffffffu, Q, 1);
        R += __shfl_xor_sync(0xffffffffu, R, 1);
        Pv += __shfl_xor_sync(0xffffffffu, Pv, 1);
        Qv += __shfl_xor_sync(0xffffffffu, Qv, 1);
        Rv += __shfl_xor_sync(0xffffffffu, Rv, 1);
        if (h == 0) {
            float* d = g_rows + (size_t)(bn + c) * 8;
            atomicAdd(d + 0, T);  atomicAdd(d + 1, P);  atomicAdd(d + 2, Q);
            atomicAdd(d + 3, R);  atomicAdd(d + 4, Pv); atomicAdd(d + 5, Qv);
            atomicAdd(d + 6, Rv);
        }
    }
}

// ---------------- assemble + finalize (single block) ----------------
// E1 = T-P; E2 = T-P-Q-R.  x = e^{-v}E >= ~700:
// sum_pos log1p(e^{-v}E) = n*logE - sum(v) + sum(e^v)/E
__global__ void assemble_final_kernel(float* out) {
    __shared__ double sd[32];
    double acc = 0.0;
    for (int i = threadIdx.x; i < NR; i += 1024) {
        const float* b = g_rows + (size_t)i * 8;
        float T = b[0], P = b[1], Q = b[2], R = b[3], Pv = b[4], Qv = b[5], Rv = b[6];
        float E1 = T - P;
        float E2 = E1 - Q - R;
        float ct = (float)g_chist[g_tcls[i >> 2]];
        float c = ct * logf(E1) - Pv + P / E1
                + (2048.0f + 2.0f * ct) * logf(E2) - (Qv + Rv) + (Q + R) / E2;
        acc += (double)c;
    }
#pragma unroll
    for (int o = 16; o > 0; o >>= 1) acc += __shfl_xor_sync(0xffffffffu, acc, o);
    const int wid = threadIdx.x >> 5, lid = threadIdx.x & 31;
    if (lid == 0) sd[wid] = acc;
    __syncthreads();
    if (wid == 0) {
        acc = sd[lid];
#pragma unroll
        for (int o = 16; o > 0; o >>= 1) acc += __shfl_xor_sync(0xffffffffu, acc, o);
        if (lid == 0)
            out[0] = (float)(g_ce / (double)BATCH + 0.5 * (acc / (double)NR));
    }
}

// ---------------- launch ----------------
extern "C" void kernel_launch(void* const* d_in, const int* in_sizes, int n_in,
                              void* d_out, int out_size) {
    const float* pred = nullptr;
    const float* x_part = nullptr;
    const unsigned int* traw = nullptr;
    for (int i = 0; i < n_in; i++) {
        if (in_sizes[i] == BATCH * NCLS)      pred   = (const float*)d_in[i];
        else if (in_sizes[i] == NR * DD)      x_part = (const float*)d_in[i];
        else if (in_sizes[i] == BATCH)        traw   = (const unsigned int*)d_in[i];
    }
    float* out = (float*)d_out;

    // dynamic smem: max(pipeline 2*2*128*72*2B = 73728B, staging 128*132*4B = 67584B)
    const int gemm_smem = 2 * 2 * 128 * LDSB * 2;
    cudaFuncSetAttribute(gemm_fused_kernel, cudaFuncAttributeMaxDynamicSharedMemorySize, gemm_smem);

    decode_targets_kernel<<<1, 1024>>>(traw);
    norm_ce_kernel<<<NR + BATCH, 128>>>(x_part, pred);
    gemm_fused_kernel<<<2080, 256, gemm_smem>>>();
    assemble_final_kernel<<<1, 1024>>>(out);
}

// round 10
// speedup vs baseline: 1.7396x; 1.0684x over previous
#include <cuda_runtime.h>
#include <cuda_bf16.h>
#include <mma.h>
#include <cstdint>
#include <math.h>

using namespace nvcuda;

#define NR 8192
#define DD 512
#define BATCH 2048
#define NCLS 200

// ---------------- scratch (__device__ globals, no allocation) ----------------
__device__ __nv_bfloat16 g_f[(size_t)NR * DD];   // normalized features (8 MB)
__device__ float g_rows[(size_t)NR * 8];         // per-row {T,P,Q,R,Pv,Qv,Rv,pad} (256 KB)
__device__ int g_chist[NCLS];
__device__ double g_ce;
__device__ double g_np;
__device__ unsigned char g_tcls[BATCH];

// ---------------- reductions ----------------
template <int BS>
__device__ __forceinline__ float blockReduceSum(float v, float* sbuf) {
#pragma unroll
    for (int o = 16; o > 0; o >>= 1) v += __shfl_xor_sync(0xffffffffu, v, o);
    int w = threadIdx.x >> 5;
    if ((threadIdx.x & 31) == 0) sbuf[w] = v;
    __syncthreads();
    if (w == 0) {
        v = (threadIdx.x < BS / 32) ? sbuf[threadIdx.x] : 0.0f;
#pragma unroll
        for (int o = 16; o > 0; o >>= 1) v += __shfl_xor_sync(0xffffffffu, v, o);
        if (threadIdx.x == 0) sbuf[0] = v;
    }
    __syncthreads();
    float r = sbuf[0];
    __syncthreads();
    return r;
}
template <int BS>
__device__ __forceinline__ float blockReduceMax(float v, float* sbuf) {
#pragma unroll
    for (int o = 16; o > 0; o >>= 1) v = fmaxf(v, __shfl_xor_sync(0xffffffffu, v, o));
    int w = threadIdx.x >> 5;
    if ((threadIdx.x & 31) == 0) sbuf[w] = v;
    __syncthreads();
    if (w == 0) {
        v = (threadIdx.x < BS / 32) ? sbuf[threadIdx.x] : -3.0e38f;
#pragma unroll
        for (int o = 16; o > 0; o >>= 1) v = fmaxf(v, __shfl_xor_sync(0xffffffffu, v, o));
        if (threadIdx.x == 0) sbuf[0] = v;
    }
    __syncthreads();
    float r = sbuf[0];
    __syncthreads();
    return r;
}

// ---------------- decode targets + class histogram ----------------
__global__ void decode_targets_kernel(const unsigned int* __restrict__ traw) {
    __shared__ int hist[NCLS];
    if (threadIdx.x == 0) { g_ce = 0.0; g_np = 0.0; }
    for (int c = threadIdx.x; c < NCLS; c += blockDim.x) hist[c] = 0;
    __syncthreads();
    int nz = 0;
    for (int i = threadIdx.x; i < BATCH / 2; i += blockDim.x)
        if (traw[2 * i + 1] != 0u) nz = 1;
    if (__syncthreads_or(nz)) {           // int32 layout
        for (int i = threadIdx.x; i < BATCH; i += blockDim.x) {
            unsigned char c = (unsigned char)traw[i];
            g_tcls[i] = c;
            atomicAdd(&hist[c], 1);
        }
    } else {                              // little-endian int64 layout
        for (int i = threadIdx.x; i < BATCH; i += blockDim.x) {
            unsigned char c = (unsigned char)traw[2 * i];
            g_tcls[i] = c;
            atomicAdd(&hist[c], 1);
        }
    }
    __syncthreads();
    for (int c = threadIdx.x; c < NCLS; c += blockDim.x) g_chist[c] = hist[c];
}

// ---------------- fused normalize + CE + g_rows zeroing ----------------
#define ZBLK 64
__global__ void norm_ce_kernel(const float* __restrict__ x, const float* __restrict__ pred) {
    __shared__ float sbuf[8];
    const int b = blockIdx.x;
    if (b < NR) {
        const float* xr = x + (size_t)b * DD;
        float s = 0.0f;
        for (int c = threadIdx.x; c < DD; c += 128) { float v = xr[c]; s += v * v; }
        s = blockReduceSum<128>(s, sbuf);
        float inv = 1.0f / fmaxf(sqrtf(s), 1e-12f);
        for (int c = threadIdx.x; c < DD; c += 128)
            g_f[(size_t)b * DD + c] = __float2bfloat16(xr[c] * inv);
    } else if (b < NR + BATCH) {
        const int i = b - NR;
        const float* p = pred + (size_t)i * NCLS;
        float m = -3.0e38f, slin = 0.0f;
        for (int c = threadIdx.x; c < NCLS; c += 128) {
            float v = p[c];
            m = fmaxf(m, v);
            slin += v;
        }
        m = blockReduceMax<128>(m, sbuf);
        slin = blockReduceSum<128>(slin, sbuf);
        float se = 0.0f;
        for (int c = threadIdx.x; c < NCLS; c += 128) se += __expf(p[c] - m);
        se = blockReduceSum<128>(se, sbuf);
        if (threadIdx.x == 0) {
            float lse = m + __logf(se);
            int t = (int)g_tcls[i];
            float loss = 0.9f * (lse - p[t]) + 0.1f * (lse - slin / (float)NCLS);
            atomicAdd(&g_ce, (double)loss);
        }
    } else {
        // zero a 1/ZBLK slice of g_rows (64K floats total / 64 blocks = 1024 floats)
        const int z = b - NR - BATCH;
        float4* dst = (float4*)(g_rows) + (size_t)z * (NR * 8 / 4 / ZBLK);
        for (int i = threadIdx.x; i < NR * 8 / 4 / ZBLK; i += 128)
            dst[i] = make_float4(0.f, 0.f, 0.f, 0.f);
    }
}

// ---------------- fused symmetric GEMM + masked reductions ----------------
__device__ __forceinline__ void cp_async16(void* smem_dst, const void* gmem_src) {
    unsigned s = (unsigned)__cvta_generic_to_shared(smem_dst);
    asm volatile("cp.async.cg.shared.global [%0], [%1], 16;\n" :: "r"(s), "l"(gmem_src));
}

#define LDSB 72         // pipeline row stride (bf16 elems), BK=64 + pad
#define LDG 132         // staging row stride (fp32 elems)
#define STG_ELEMS (128 * LDSB)          // per-tensor per-stage bf16 elems
#define STAGE_ELEMS (2 * STG_ELEMS)     // A+B per stage

__global__ void __launch_bounds__(256) gemm_fused_kernel() {
    extern __shared__ char dsm[];
    __nv_bfloat16* sm = (__nv_bfloat16*)dsm;          // [3][A:128*LDSB | B:128*LDSB]
    float* stg = (float*)dsm;                         // 128*LDG fp32 (reused)
    __shared__ unsigned char gA[32], gB[32];          // per-group (4 rows) class codes

    constexpr int NKIT = DD / 64;                     // 8 K-iterations

    // triangular tile decode: blockIdx.x in [0, 2080)
    int idx = blockIdx.x;
    int r = 0;
    while (idx >= 64 - r) { idx -= 64 - r; r++; }
    const int bm = r * 128;
    const int bn = (r + idx) * 128;

    const int tid = threadIdx.x;
    const int warp = tid >> 5;
    const int wm = (warp & 3) * 32;
    const int wn = (warp >> 2) * 64;

    auto load_stage = [&](int k0, int s) {
        __nv_bfloat16* As = sm + s * STAGE_ELEMS;
        __nv_bfloat16* Bs = As + STG_ELEMS;
#pragma unroll
        for (int it = 0; it < 4; it++) {
            int c = it * 256 + tid;                   // 1024 chunks of 16B per tensor
            int row = c >> 3;
            int col = (c & 7) * 8;
            cp_async16(&As[row * LDSB + col], g_f + (size_t)(bm + row) * DD + k0 * 64 + col);
            cp_async16(&Bs[row * LDSB + col], g_f + (size_t)(bn + row) * DD + k0 * 64 + col);
        }
    };

    wmma::fragment<wmma::accumulator, 16, 16, 16, float> acc[2][4];
#pragma unroll
    for (int i = 0; i < 2; i++)
#pragma unroll
        for (int j = 0; j < 4; j++) wmma::fill_fragment(acc[i][j], 0.0f);

    load_stage(0, 0);
    asm volatile("cp.async.commit_group;\n");
    load_stage(1, 1);
    asm volatile("cp.async.commit_group;\n");

    for (int k0 = 0; k0 < NKIT; k0++) {
        if (k0 < NKIT - 1) asm volatile("cp.async.wait_group 1;\n");
        else               asm volatile("cp.async.wait_group 0;\n");
        __syncthreads();                               // all warps done reading stage (k0-1)%3
        if (k0 + 2 < NKIT) {
            load_stage(k0 + 2, (k0 + 2) % 3);          // writes stage (k0-1)%3 — safe
            asm volatile("cp.async.commit_group;\n");
        }
        const int s = k0 % 3;
        const __nv_bfloat16* As = sm + s * STAGE_ELEMS;
        const __nv_bfloat16* Bs = As + STG_ELEMS;
#pragma unroll
        for (int kk = 0; kk < 4; kk++) {
            wmma::fragment<wmma::matrix_a, 16, 16, 16, __nv_bfloat16, wmma::row_major> a[2];
            wmma::fragment<wmma::matrix_b, 16, 16, 16, __nv_bfloat16, wmma::col_major> b[4];
#pragma unroll
            for (int i = 0; i < 2; i++)
                wmma::load_matrix_sync(a[i], &As[(wm + i * 16) * LDSB + kk * 16], LDSB);
#pragma unroll
            for (int j = 0; j < 4; j++)
                wmma::load_matrix_sync(b[j], &Bs[(wn + j * 16) * LDSB + kk * 16], LDSB);
#pragma unroll
            for (int i = 0; i < 2; i++)
#pragma unroll
                for (int j = 0; j < 4; j++) wmma::mma_sync(acc[i][j], a[i], b[j], acc[i][j]);
        }
    }
    __syncthreads();                                   // before reusing smem as staging

    // stage fp32 tile in smem
#pragma unroll
    for (int i = 0; i < 2; i++)
#pragma unroll
        for (int j = 0; j < 4; j++)
            wmma::store_matrix_sync(stg + (size_t)(wm + i * 16) * LDG + wn + j * 16,
                                    acc[i][j], LDG, wmma::mem_row_major);
    if (tid < 32) gA[tid] = g_tcls[(bm >> 2) + tid];
    else if (tid < 64) gB[tid - 32] = g_tcls[(bn >> 2) + (tid - 32)];
    __syncthreads();

    // ---- row pass: 2 threads per anchor row (bm+a); groups of 4 cols share class ----
    {
        const int a = tid >> 1, h = tid & 1;
        const int myc = gA[a >> 2], pi = a & 3;
        float T = 0.f, P = 0.f, Q = 0.f, R = 0.f, Pv = 0.f, Qv = 0.f, Rv = 0.f;
        const float4* rp = (const float4*)(stg + (size_t)a * LDG + h * 64);
#pragma unroll
        for (int g = 0; g < 16; g++) {
            float4 v4 = rp[g];
            float e0 = __expf(v4.x), e1 = __expf(v4.y), e2 = __expf(v4.z), e3 = __expf(v4.w);
            float s = (e0 + e1) + (e2 + e3);
            float vs = (v4.x + v4.y) + (v4.z + v4.w);
            float ep = pi == 0 ? e0 : pi == 1 ? e1 : pi == 2 ? e2 : e3;
            float vp = pi == 0 ? v4.x : pi == 1 ? v4.y : pi == 2 ? v4.z : v4.w;
            float m = (gB[h * 16 + g] == myc) ? 1.0f : 0.0f;
            T += s;
            P += m * ep;          Pv += m * vp;
            R += m * (s - ep);    Rv += m * (vs - vp);
            Q += (1.0f - m) * ep; Qv += (1.0f - m) * vp;
        }
        T += __shfl_xor_sync(0xffffffffu, T, 1);
        P += __shfl_xor_sync(0xffffffffu, P, 1);
        Q += __shfl_xor_sync(0xffffffffu, Q, 1);
        R += __shfl_xor_sync(0xffffffffu, R, 1);
        Pv += __shfl_xor_sync(0xffffffffu, Pv, 1);
        Qv += __shfl_xor_sync(0xffffffffu, Qv, 1);
        Rv += __shfl_xor_sync(0xffffffffu, Rv, 1);
        if (h == 0) {
            float* d = g_rows + (size_t)(bm + a) * 8;
            atomicAdd(d + 0, T);  atomicAdd(d + 1, P);  atomicAdd(d + 2, Q);
            atomicAdd(d + 3, R);  atomicAdd(d + 4, Pv); atomicAdd(d + 5, Qv);
            atomicAdd(d + 6, Rv);
        }
    }

    // ---- col pass (off-diagonal only): anchors bn+c over rows of bm block ----
    if (bm != bn) {
        const int c = tid >> 1, h = tid & 1;
        const int myc = gB[c >> 2], pi = c & 3;
        float T = 0.f, P = 0.f, Q = 0.f, R = 0.f, Pv = 0.f, Qv = 0.f, Rv = 0.f;
#pragma unroll
        for (int g = 0; g < 16; g++) {
            const int j0 = h * 64 + g * 4;
            float v0 = stg[(j0 + 0) * LDG + c];
            float v1 = stg[(j0 + 1) * LDG + c];
            float v2 = stg[(j0 + 2) * LDG + c];
            float v3 = stg[(j0 + 3) * LDG + c];
            float e0 = __expf(v0), e1 = __expf(v1), e2 = __expf(v2), e3 = __expf(v3);
            float s = (e0 + e1) + (e2 + e3);
            float vs = (v0 + v1) + (v2 + v3);
            float ep = pi == 0 ? e0 : pi == 1 ? e1 : pi == 2 ? e2 : e3;
            float vp = pi == 0 ? v0 : pi == 1 ? v1 : pi == 2 ? v2 : v3;
            float m = (gA[h * 16 + g] == myc) ? 1.0f : 0.0f;
            T += s;
            P += m * ep;          Pv += m * vp;
            R += m * (s - ep);    Rv += m * (vs - vp);
            Q += (1.0f - m) * ep; Qv += (1.0f - m) * vp;
        }
        T += __shfl_xor_sync(0xffffffffu, T, 1);
        P += __shfl_xor_sync(0xffffffffu, P, 1);
        Q += __shfl_xor_sync(0xffffffffu, Q, 1);
        R += __shfl_xor_sync(0xffffffffu, R, 1);
        Pv += __shfl_xor_sync(0xffffffffu, Pv, 1);
        Qv += __shfl_xor_sync(0xffffffffu, Qv, 1);
        Rv += __shfl_xor_sync(0xffffffffu, Rv, 1);
        if (h == 0) {
            float* d = g_rows + (size_t)(bn + c) * 8;
            atomicAdd(d + 0, T);  atomicAdd(d + 1, P);  atomicAdd(d + 2, Q);
            atomicAdd(d + 3, R);  atomicAdd(d + 4, Pv); atomicAdd(d + 5, Qv);
            atomicAdd(d + 6, Rv);
        }
    }
}

// ---------------- assemble (32 blocks) + finalize ----------------
// E1 = T-P; E2 = T-P-Q-R.  x = e^{-v}E >= ~700:
// sum_pos log1p(e^{-v}E) = n*logE - sum(v) + sum(e^v)/E
__global__ void assemble_kernel() {
    const int i = blockIdx.x * 256 + threadIdx.x;      // 8192 threads over 32 blocks
    const float* b = g_rows + (size_t)i * 8;
    float T = b[0], P = b[1], Q = b[2], R = b[3], Pv = b[4], Qv = b[5], Rv = b[6];
    float E1 = T - P;
    float E2 = E1 - Q - R;
    float ct = (float)g_chist[g_tcls[i >> 2]];
    float c = ct * __logf(E1) - Pv + P / E1
            + (2048.0f + 2.0f * ct) * __logf(E2) - (Qv + Rv) + (Q + R) / E2;
    double d = (double)c;
#pragma unroll
    for (int o = 16; o > 0; o >>= 1) d += __shfl_xor_sync(0xffffffffu, d, o);
    if ((threadIdx.x & 31) == 0) atomicAdd(&g_np, d);
}

__global__ void finalize_kernel(float* out) {
    out[0] = (float)(g_ce / (double)BATCH + 0.5 * (g_np / (double)NR));
}

// ---------------- launch ----------------
extern "C" void kernel_launch(void* const* d_in, const int* in_sizes, int n_in,
                              void* d_out, int out_size) {
    const float* pred = nullptr;
    const float* x_part = nullptr;
    const unsigned int* traw = nullptr;
    for (int i = 0; i < n_in; i++) {
        if (in_sizes[i] == BATCH * NCLS)      pred   = (const float*)d_in[i];
        else if (in_sizes[i] == NR * DD)      x_part = (const float*)d_in[i];
        else if (in_sizes[i] == BATCH)        traw   = (const unsigned int*)d_in[i];
    }
    float* out = (float*)d_out;

    // dynamic smem: max(3-stage pipeline 3*2*128*72*2B = 110592B, staging 67584B)
    const int gemm_smem = 3 * STAGE_ELEMS * 2;
    cudaFuncSetAttribute(gemm_fused_kernel, cudaFuncAttributeMaxDynamicSharedMemorySize, gemm_smem);

    decode_targets_kernel<<<1, 1024>>>(traw);
    norm_ce_kernel<<<NR + BATCH + ZBLK, 128>>>(x_part, pred);
    gemm_fused_kernel<<<2080, 256, gemm_smem>>>();
    assemble_kernel<<<32, 256>>>();
    finalize_kernel<<<1, 1>>>(out);
}

// round 11
// speedup vs baseline: 2.1015x; 1.2080x over previous
#include <cuda_runtime.h>
#include <cuda_bf16.h>
#include <mma.h>
#include <cstdint>
#include <math.h>

using namespace nvcuda;

#define NR 8192
#define DD 512
#define BATCH 2048
#define NCLS 200

// ---------------- scratch (__device__ globals, no allocation) ----------------
__device__ signed char g_q[(size_t)NR * DD];     // quantized normalized features (4 MB)
__device__ float g_rows[(size_t)NR * 8];         // per-row {T,P,Q,R,Pv,Qv,Rv,pad} (256 KB)
__device__ int g_chist[NCLS];
__device__ double g_ce;
__device__ double g_np;
__device__ unsigned g_done;
__device__ unsigned char g_tcls[BATCH];

// ---------------- reductions ----------------
template <int BS>
__device__ __forceinline__ float blockReduceSum(float v, float* sbuf) {
#pragma unroll
    for (int o = 16; o > 0; o >>= 1) v += __shfl_xor_sync(0xffffffffu, v, o);
    int w = threadIdx.x >> 5;
    if ((threadIdx.x & 31) == 0) sbuf[w] = v;
    __syncthreads();
    if (w == 0) {
        v = (threadIdx.x < BS / 32) ? sbuf[threadIdx.x] : 0.0f;
#pragma unroll
        for (int o = 16; o > 0; o >>= 1) v += __shfl_xor_sync(0xffffffffu, v, o);
        if (threadIdx.x == 0) sbuf[0] = v;
    }
    __syncthreads();
    float r = sbuf[0];
    __syncthreads();
    return r;
}
template <int BS>
__device__ __forceinline__ float blockReduceMax(float v, float* sbuf) {
#pragma unroll
    for (int o = 16; o > 0; o >>= 1) v = fmaxf(v, __shfl_xor_sync(0xffffffffu, v, o));
    int w = threadIdx.x >> 5;
    if ((threadIdx.x & 31) == 0) sbuf[w] = v;
    __syncthreads();
    if (w == 0) {
        v = (threadIdx.x < BS / 32) ? sbuf[threadIdx.x] : -3.0e38f;
#pragma unroll
        for (int o = 16; o > 0; o >>= 1) v = fmaxf(v, __shfl_xor_sync(0xffffffffu, v, o));
        if (threadIdx.x == 0) sbuf[0] = v;
    }
    __syncthreads();
    float r = sbuf[0];
    __syncthreads();
    return r;
}

// ---------------- decode targets + class histogram ----------------
__global__ void decode_targets_kernel(const unsigned int* __restrict__ traw) {
    __shared__ int hist[NCLS];
    if (threadIdx.x == 0) { g_ce = 0.0; g_np = 0.0; g_done = 0u; }
    for (int c = threadIdx.x; c < NCLS; c += blockDim.x) hist[c] = 0;
    __syncthreads();
    int nz = 0;
    for (int i = threadIdx.x; i < BATCH / 2; i += blockDim.x)
        if (traw[2 * i + 1] != 0u) nz = 1;
    if (__syncthreads_or(nz)) {           // int32 layout
        for (int i = threadIdx.x; i < BATCH; i += blockDim.x) {
            unsigned char c = (unsigned char)traw[i];
            g_tcls[i] = c;
            atomicAdd(&hist[c], 1);
        }
    } else {                              // little-endian int64 layout
        for (int i = threadIdx.x; i < BATCH; i += blockDim.x) {
            unsigned char c = (unsigned char)traw[2 * i];
            g_tcls[i] = c;
            atomicAdd(&hist[c], 1);
        }
    }
    __syncthreads();
    for (int c = threadIdx.x; c < NCLS; c += blockDim.x) g_chist[c] = hist[c];
}

// ---------------- fused normalize(+quantize) + CE + g_rows zeroing ----------------
#define ZBLK 64
__global__ void norm_ce_kernel(const float* __restrict__ x, const float* __restrict__ pred) {
    __shared__ float sbuf[8];
    const int b = blockIdx.x;
    if (b < NR) {
        const float* xr = x + (size_t)b * DD;
        float s = 0.0f;
        for (int c = threadIdx.x; c < DD; c += 128) { float v = xr[c]; s += v * v; }
        s = blockReduceSum<128>(s, sbuf);
        float inv = 127.0f / fmaxf(sqrtf(s), 1e-12f);
        for (int c = threadIdx.x; c < DD; c += 128)
            g_q[(size_t)b * DD + c] = (signed char)__float2int_rn(xr[c] * inv);
    } else if (b < NR + BATCH) {
        const int i = b - NR;
        const float* p = pred + (size_t)i * NCLS;
        float m = -3.0e38f, slin = 0.0f;
        for (int c = threadIdx.x; c < NCLS; c += 128) {
            float v = p[c];
            m = fmaxf(m, v);
            slin += v;
        }
        m = blockReduceMax<128>(m, sbuf);
        slin = blockReduceSum<128>(slin, sbuf);
        float se = 0.0f;
        for (int c = threadIdx.x; c < NCLS; c += 128) se += __expf(p[c] - m);
        se = blockReduceSum<128>(se, sbuf);
        if (threadIdx.x == 0) {
            float lse = m + __logf(se);
            int t = (int)g_tcls[i];
            float loss = 0.9f * (lse - p[t]) + 0.1f * (lse - slin / (float)NCLS);
            atomicAdd(&g_ce, (double)loss);
        }
    } else {
        const int z = b - NR - BATCH;
        float4* dst = (float4*)(g_rows) + (size_t)z * (NR * 8 / 4 / ZBLK);
        for (int i = threadIdx.x; i < NR * 8 / 4 / ZBLK; i += 128)
            dst[i] = make_float4(0.f, 0.f, 0.f, 0.f);
    }
}

// ---------------- fused symmetric int8 GEMM + masked reductions ----------------
__device__ __forceinline__ void cp_async16(void* smem_dst, const void* gmem_src) {
    unsigned s = (unsigned)__cvta_generic_to_shared(smem_dst);
    asm volatile("cp.async.cg.shared.global [%0], [%1], 16;\n" :: "r"(s), "l"(gmem_src));
}

#define LDSB 80         // int8 row stride bytes: 64 + 16 pad (conflict-free LDSM)
#define LDG 132         // staging row stride (int32 elems)
#define STG_ELEMS (128 * LDSB)          // per-tensor per-stage bytes
#define STAGE_ELEMS (2 * STG_ELEMS)     // A+B per stage (20480 B)
#define INV_Q2 (1.0f / 16129.0f)        // 1/127^2

__global__ void __launch_bounds__(256) gemm_fused_kernel() {
    extern __shared__ char dsm[];
    signed char* sm = (signed char*)dsm;              // [3][A:128*80 | B:128*80]
    int* stgi = (int*)dsm;                            // 128*LDG int32 (reused)
    __shared__ unsigned char gA[32], gB[32];          // per-group (4 rows) class codes

    constexpr int NKIT = DD / 64;                     // 8 K-iterations

    // triangular tile decode: blockIdx.x in [0, 2080)
    int idx = blockIdx.x;
    int r = 0;
    while (idx >= 64 - r) { idx -= 64 - r; r++; }
    const int bm = r * 128;
    const int bn = (r + idx) * 128;

    const int tid = threadIdx.x;
    const int warp = tid >> 5;
    const int wm = (warp & 3) * 32;
    const int wn = (warp >> 2) * 64;

    auto load_stage = [&](int k0, int s) {
        signed char* As = sm + s * STAGE_ELEMS;
        signed char* Bs = As + STG_ELEMS;
#pragma unroll
        for (int it = 0; it < 2; it++) {
            int c = it * 256 + tid;                   // 512 chunks of 16B per tensor
            int row = c >> 2;
            int col = (c & 3) * 16;
            cp_async16(&As[row * LDSB + col], g_q + (size_t)(bm + row) * DD + k0 * 64 + col);
            cp_async16(&Bs[row * LDSB + col], g_q + (size_t)(bn + row) * DD + k0 * 64 + col);
        }
    };

    wmma::fragment<wmma::accumulator, 16, 16, 16, int> acc[2][4];
#pragma unroll
    for (int i = 0; i < 2; i++)
#pragma unroll
        for (int j = 0; j < 4; j++) wmma::fill_fragment(acc[i][j], 0);

    load_stage(0, 0);
    asm volatile("cp.async.commit_group;\n");
    load_stage(1, 1);
    asm volatile("cp.async.commit_group;\n");

    for (int k0 = 0; k0 < NKIT; k0++) {
        if (k0 < NKIT - 1) asm volatile("cp.async.wait_group 1;\n");
        else               asm volatile("cp.async.wait_group 0;\n");
        __syncthreads();                               // all warps done reading stage (k0-1)%3
        if (k0 + 2 < NKIT) {
            load_stage(k0 + 2, (k0 + 2) % 3);          // overwrites stage (k0-1)%3 — safe
            asm volatile("cp.async.commit_group;\n");
        }
        const int s = k0 % 3;
        const signed char* As = sm + s * STAGE_ELEMS;
        const signed char* Bs = As + STG_ELEMS;
#pragma unroll
        for (int kk = 0; kk < 4; kk++) {
            wmma::fragment<wmma::matrix_a, 16, 16, 16, signed char, wmma::row_major> a[2];
            wmma::fragment<wmma::matrix_b, 16, 16, 16, signed char, wmma::col_major> b[4];
#pragma unroll
            for (int i = 0; i < 2; i++)
                wmma::load_matrix_sync(a[i], &As[(wm + i * 16) * LDSB + kk * 16], LDSB);
#pragma unroll
            for (int j = 0; j < 4; j++)
                wmma::load_matrix_sync(b[j], &Bs[(wn + j * 16) * LDSB + kk * 16], LDSB);
#pragma unroll
            for (int i = 0; i < 2; i++)
#pragma unroll
                for (int j = 0; j < 4; j++) wmma::mma_sync(acc[i][j], a[i], b[j], acc[i][j]);
        }
    }
    __syncthreads();                                   // before reusing smem as staging

    // stage int32 tile in smem
#pragma unroll
    for (int i = 0; i < 2; i++)
#pragma unroll
        for (int j = 0; j < 4; j++)
            wmma::store_matrix_sync(stgi + (size_t)(wm + i * 16) * LDG + wn + j * 16,
                                    acc[i][j], LDG, wmma::mem_row_major);
    if (tid < 32) gA[tid] = g_tcls[(bm >> 2) + tid];
    else if (tid < 64) gB[tid - 32] = g_tcls[(bn >> 2) + (tid - 32)];
    __syncthreads();

    // ---- row pass: 2 threads per anchor row (bm+a); groups of 4 cols share class ----
    {
        const int a = tid >> 1, h = tid & 1;
        const int myc = gA[a >> 2], pi = a & 3;
        float T = 0.f, P = 0.f, Q = 0.f, R = 0.f, Pv = 0.f, Qv = 0.f, Rv = 0.f;
        const int4* rp = (const int4*)(stgi + (size_t)a * LDG + h * 64);
#pragma unroll
        for (int g = 0; g < 16; g++) {
            int4 q4 = rp[g];
            float v0 = (float)q4.x * INV_Q2, v1 = (float)q4.y * INV_Q2;
            float v2 = (float)q4.z * INV_Q2, v3 = (float)q4.w * INV_Q2;
            float e0 = __expf(v0), e1 = __expf(v1), e2 = __expf(v2), e3 = __expf(v3);
            float s = (e0 + e1) + (e2 + e3);
            float vs = (v0 + v1) + (v2 + v3);
            float ep = pi == 0 ? e0 : pi == 1 ? e1 : pi == 2 ? e2 : e3;
            float vp = pi == 0 ? v0 : pi == 1 ? v1 : pi == 2 ? v2 : v3;
            float m = (gB[h * 16 + g] == myc) ? 1.0f : 0.0f;
            T += s;
            P += m * ep;          Pv += m * vp;
            R += m * (s - ep);    Rv += m * (vs - vp);
            Q += (1.0f - m) * ep; Qv += (1.0f - m) * vp;
        }
        T += __shfl_xor_sync(0xffffffffu, T, 1);
        P += __shfl_xor_sync(0xffffffffu, P, 1);
        Q += __shfl_xor_sync(0xffffffffu, Q, 1);
        R += __shfl_xor_sync(0xffffffffu, R, 1);
        Pv += __shfl_xor_sync(0xffffffffu, Pv, 1);
        Qv += __shfl_xor_sync(0xffffffffu, Qv, 1);
        Rv += __shfl_xor_sync(0xffffffffu, Rv, 1);
        if (h == 0) {
            float* d = g_rows + (size_t)(bm + a) * 8;
            atomicAdd(d + 0, T);  atomicAdd(d + 1, P);  atomicAdd(d + 2, Q);
            atomicAdd(d + 3, R);  atomicAdd(d + 4, Pv); atomicAdd(d + 5, Qv);
            atomicAdd(d + 6, Rv);
        }
    }

    // ---- col pass (off-diagonal only): anchors bn+c over rows of bm block ----
    if (bm != bn) {
        const int c = tid >> 1, h = tid & 1;
        const int myc = gB[c >> 2], pi = c & 3;
        float T = 0.f, P = 0.f, Q = 0.f, R = 0.f, Pv = 0.f, Qv = 0.f, Rv = 0.f;
#pragma unroll
        for (int g = 0; g < 16; g++) {
            const int j0 = h * 64 + g * 4;
            float v0 = (float)stgi[(j0 + 0) * LDG + c] * INV_Q2;
            float v1 = (float)stgi[(j0 + 1) * LDG + c] * INV_Q2;
            float v2 = (float)stgi[(j0 + 2) * LDG + c] * INV_Q2;
            float v3 = (float)stgi[(j0 + 3) * LDG + c] * INV_Q2;
            float e0 = __expf(v0), e1 = __expf(v1), e2 = __expf(v2), e3 = __expf(v3);
            float s = (e0 + e1) + (e2 + e3);
            float vs = (v0 + v1) + (v2 + v3);
            float ep = pi == 0 ? e0 : pi == 1 ? e1 : pi == 2 ? e2 : e3;
            float vp = pi == 0 ? v0 : pi == 1 ? v1 : pi == 2 ? v2 : v3;
            float m = (gA[h * 16 + g] == myc) ? 1.0f : 0.0f;
            T += s;
            P += m * ep;          Pv += m * vp;
            R += m * (s - ep);    Rv += m * (vs - vp);
            Q += (1.0f - m) * ep; Qv += (1.0f - m) * vp;
        }
        T += __shfl_xor_sync(0xffffffffu, T, 1);
        P += __shfl_xor_sync(0xffffffffu, P, 1);
        Q += __shfl_xor_sync(0xffffffffu, Q, 1);
        R += __shfl_xor_sync(0xffffffffu, R, 1);
        Pv += __shfl_xor_sync(0xffffffffu, Pv, 1);
        Qv += __shfl_xor_sync(0xffffffffu, Qv, 1);
        Rv += __shfl_xor_sync(0xffffffffu, Rv, 1);
        if (h == 0) {
            float* d = g_rows + (size_t)(bn + c) * 8;
            atomicAdd(d + 0, T);  atomicAdd(d + 1, P);  atomicAdd(d + 2, Q);
            atomicAdd(d + 3, R);  atomicAdd(d + 4, Pv); atomicAdd(d + 5, Qv);
            atomicAdd(d + 6, Rv);
        }
    }
}

// ---------------- assemble (32 blocks) + last-block finalize ----------------
// E1 = T-P; E2 = T-P-Q-R.  x = e^{-v}E >= ~700:
// sum_pos log1p(e^{-v}E) = n*logE - sum(v) + sum(e^v)/E
__global__ void assemble_kernel(float* out) {
    const int i = blockIdx.x * 256 + threadIdx.x;      // 8192 threads over 32 blocks
    const float* b = g_rows + (size_t)i * 8;
    float T = b[0], P = b[1], Q = b[2], R = b[3], Pv = b[4], Qv = b[5], Rv = b[6];
    float E1 = T - P;
    float E2 = E1 - Q - R;
    float ct = (float)g_chist[g_tcls[i >> 2]];
    float c = ct * __logf(E1) - Pv + P / E1
            + (2048.0f + 2.0f * ct) * __logf(E2) - (Qv + Rv) + (Q + R) / E2;
    double d = (double)c;
#pragma unroll
    for (int o = 16; o > 0; o >>= 1) d += __shfl_xor_sync(0xffffffffu, d, o);
    if ((threadIdx.x & 31) == 0) atomicAdd(&g_np, d);
    __syncthreads();
    if (threadIdx.x == 0) {
        __threadfence();
        unsigned done = atomicAdd(&g_done, 1u);
        if (done == 31u) {                             // last block finalizes
            __threadfence();
            double np = atomicAdd(&g_np, 0.0);         // ordered read
            double ce = g_ce;
            out[0] = (float)(ce / (double)BATCH + 0.5 * (np / (double)NR));
            g_done = 0u;                               // reset for next replay
        }
    }
}

// ---------------- launch ----------------
extern "C" void kernel_launch(void* const* d_in, const int* in_sizes, int n_in,
                              void* d_out, int out_size) {
    const float* pred = nullptr;
    const float* x_part = nullptr;
    const unsigned int* traw = nullptr;
    for (int i = 0; i < n_in; i++) {
        if (in_sizes[i] == BATCH * NCLS)      pred   = (const float*)d_in[i];
        else if (in_sizes[i] == NR * DD)      x_part = (const float*)d_in[i];
        else if (in_sizes[i] == BATCH)        traw   = (const unsigned int*)d_in[i];
    }
    float* out = (float*)d_out;

    // dynamic smem: max(3-stage int8 pipeline 3*20480 = 61440, staging 128*132*4 = 67584)
    const int gemm_smem = 128 * LDG * 4;
    cudaFuncSetAttribute(gemm_fused_kernel, cudaFuncAttributeMaxDynamicSharedMemorySize, gemm_smem);

    decode_targets_kernel<<<1, 1024>>>(traw);
    norm_ce_kernel<<<NR + BATCH + ZBLK, 128>>>(x_part, pred);
    gemm_fused_kernel<<<2080, 256, gemm_smem>>>();
    assemble_kernel<<<32, 256>>>(out);
}